// round 10
// baseline (speedup 1.0000x reference)
#include <cuda_runtime.h>
#include <cstddef>

// KitNET_5257039970983 — R9: quadratic-form fold (err = x'Sx + c'x + k, S=M^2),
// triangular packed constants, fully unrolled tile loop, ping-pong slices with
// one syncwarp/iter. R7/R8 skeleton otherwise (constant bank, warp-local, no
// block barriers).
// Output: head_out(B,10) then tails(B,10), fp32.

#define NTILES 10
#define CDIM   10
#define HDIM   7
#define FDIM   100
#define TPB    256
#define RPB    512
#define PSF    28                 // floats per pair slot (112B): h0[0..11] h1[12..23] pad
#define SLICE_F (32*PSF)          // 896 floats per warp per buffer

typedef unsigned long long u64;

// triangular row offsets (in ulonglong2) within a tile's 35-entry UT block,
// and pair-counts per row.  Row i = [c_i, U_ii, U_i(i+1)... U_i9, pad?]
__device__ constexpr int ROFF[10] = {0, 6, 11, 16, 20, 24, 27, 30, 32, 34};
__device__ constexpr int QI[10]   = {6, 5, 5, 4, 4, 3, 3, 2, 2, 1};

struct FoldData {
    ulonglong2 UT[350];   // [t][35] triangular rows, values packed (v,v)
    u64        KT[10];    // (k,k)
    ulonglong2 MH[50];    // head fold [j][i pair]
    ulonglong2 BH[5];
    int perm[100];
    int tbase[10];
    int pad[2];
};

__device__   FoldData gF;
__constant__ FoldData cF;

__device__ __forceinline__ u64 fma2(u64 a, u64 b, u64 c) {
    u64 d;
    asm("fma.rn.f32x2 %0, %1, %2, %3;" : "=l"(d) : "l"(a), "l"(b), "l"(c));
    return d;
}
__device__ __forceinline__ u64 pack2(float x, float y) {
    u64 d;
    asm("mov.b64 %0, {%1, %2};" : "=l"(d) : "f"(x), "f"(y));
    return d;
}
__device__ __forceinline__ void unpack2(u64 a, float& x, float& y) {
    asm("mov.b64 {%0, %1}, %2;" : "=f"(x), "=f"(y) : "l"(a));
}
__device__ __forceinline__ float lg2f(float v) {
    float r;
    asm("lg2.approx.f32 %0, %1;" : "=f"(r) : "f"(v));
    return r;
}

// ================= setup kernel: fold weights into gF (1 block) =================
__global__ void kitnet_setup(const float* __restrict__ Wt,
                             const float* __restrict__ hbt,
                             const float* __restrict__ vbt,
                             const float* __restrict__ Wh,
                             const float* __restrict__ hbh,
                             const float* __restrict__ vbh,
                             const int*   __restrict__ clusters)
{
    __shared__ float sW[700], sHB[70], sVB[100], sWH[70], sHBH[7], sVBH[10];
    __shared__ float sM[1000], sB[100];
    const int tid = threadIdx.x;
    for (int i = tid; i < 700; i += TPB) sW[i]  = Wt[i];
    for (int i = tid; i < 70;  i += TPB) sHB[i] = hbt[i];
    for (int i = tid; i < 100; i += TPB) sVB[i] = vbt[i];
    for (int i = tid; i < 70;  i += TPB) sWH[i] = Wh[i];
    if (tid < HDIM)   sHBH[tid] = hbh[tid];
    if (tid < NTILES) sVBH[tid] = vbh[tid];
    __syncthreads();

    // M = W^T W - I (per tile), b = W^T hb + vb
    for (int i = tid; i < 1000; i += TPB) {
        int t  = i / 100;
        int r  = i - t * 100;
        int co = r / 10;
        int ci = r - co * 10;
        float m = (ci == co) ? -1.0f : 0.0f;
        #pragma unroll
        for (int h = 0; h < HDIM; ++h)
            m += sW[t * 70 + h * 10 + ci] * sW[t * 70 + h * 10 + co];
        sM[i] = m;
    }
    for (int i = tid; i < 100; i += TPB) {
        int t = i / 10, c = i - t * 10;
        float b = sVB[i];
        #pragma unroll
        for (int h = 0; h < HDIM; ++h)
            b += sHB[t * HDIM + h] * sW[t * 70 + h * 10 + c];
        sB[i] = b;
    }
    __syncthreads();

    // quadratic fold: S = M^2 (sym), c = 2 M b, k = b.b ; triangular packing
    if (tid < 100) {
        int t = tid / 10, i = tid - (tid / 10) * 10;
        const float* Mt = sM + t * 100;
        const float* bt = sB + t * 10;
        float c = 0.0f;
        #pragma unroll
        for (int m = 0; m < 10; ++m) c += Mt[i * 10 + m] * bt[m];
        c *= 2.0f;
        float e[12];
        #pragma unroll
        for (int z = 0; z < 12; ++z) e[z] = 0.0f;
        e[0] = c;
        for (int j = i; j < 10; ++j) {
            float s = 0.0f;
            #pragma unroll
            for (int m = 0; m < 10; ++m) s += Mt[i * 10 + m] * Mt[m * 10 + j];
            e[1 + (j - i)] = (j == i) ? s : 2.0f * s;
        }
        int off = t * 35 + ROFF[i];
        int q   = QI[i];
        for (int p = 0; p < q; ++p) {
            ulonglong2 w;
            w.x = pack2(e[2 * p],     e[2 * p]);
            w.y = pack2(e[2 * p + 1], e[2 * p + 1]);
            gF.UT[off + p] = w;
        }
    }
    if (tid < NTILES) {
        const float* bt = sB + tid * 10;
        float k = 0.0f;
        #pragma unroll
        for (int m = 0; m < 10; ++m) k += bt[m] * bt[m];
        gF.KT[tid] = pack2(k, k);
    }

    // head fold: MH[j][i] = sum_h Wh[h][i] Wh[h][j]; BH[j] = vbh[j] + sum hbh Wh
    float2* MH2 = (float2*)gF.MH;
    float2* BH2 = (float2*)gF.BH;
    for (int i = tid; i < CDIM * CDIM; i += TPB) {
        int j = i / 10, ii = i - j * 10;
        float m = 0.0f;
        #pragma unroll
        for (int h = 0; h < HDIM; ++h)
            m += sWH[h * 10 + ii] * sWH[h * 10 + j];
        MH2[i] = make_float2(m, m);
    }
    if (tid < NTILES) {
        float b = sVBH[tid];
        #pragma unroll
        for (int h = 0; h < HDIM; ++h)
            b += sHBH[h] * sWH[h * 10 + tid];
        BH2[tid] = make_float2(b, b);
    }
    for (int i = tid; i < FDIM; i += TPB) gF.perm[i] = clusters[i];
    if (tid < NTILES) {
        const int* pp = clusters + tid * 10;
        int b0 = pp[0];
        bool ok = ((b0 & 1) == 0);
        #pragma unroll
        for (int j = 1; j < 10; ++j) ok = ok && (pp[j] == b0 + j);
        gF.tbase[tid] = ok ? b0 : -1;
    }
}

// ================= main kernel =================

// err = x'Sx + c'x + k from triangular constant block (tile t must be a
// compile-time constant at each inlined call site for immediate offsets)
__device__ __forceinline__ u64 compute_tile_q(const float* __restrict__ s0, int t)
{
    float4 a0 = *(const float4*)(s0);
    float4 a1 = *(const float4*)(s0 + 4);
    float4 a2 = *(const float4*)(s0 + 8);
    float4 b0 = *(const float4*)(s0 + 12);
    float4 b1 = *(const float4*)(s0 + 16);
    float4 b2 = *(const float4*)(s0 + 20);
    u64 xc[CDIM];
    xc[0] = pack2(a0.x, b0.x); xc[1] = pack2(a0.y, b0.y);
    xc[2] = pack2(a0.z, b0.z); xc[3] = pack2(a0.w, b0.w);
    xc[4] = pack2(a1.x, b1.x); xc[5] = pack2(a1.y, b1.y);
    xc[6] = pack2(a1.z, b1.z); xc[7] = pack2(a1.w, b1.w);
    xc[8] = pack2(a2.x, b2.x); xc[9] = pack2(a2.y, b2.y);

    const ulonglong2* R = cF.UT + t * 35;
    u64 err = cF.KT[t];
    #pragma unroll
    for (int i = 0; i < 10; ++i) {
        const ulonglong2* Ri = R + ROFF[i];
        ulonglong2 w = Ri[0];
        u64 acc = w.x;                       // c_i
        acc = fma2(xc[i], w.y, acc);         // + U_ii * x_i
        #pragma unroll
        for (int p = 1; p < QI[i]; ++p) {
            w = Ri[p];
            acc = fma2(xc[i + 2*p - 1], w.x, acc);
            if (i + 2*p <= 9)
                acc = fma2(xc[i + 2*p], w.y, acc);
        }
        err = fma2(xc[i], acc, err);
    }
    return err;
}

template<bool FULL>
__device__ __forceinline__ void run_rows(const float* __restrict__ x,
                                         float* __restrict__ out,
                                         float* __restrict__ sA,
                                         float* __restrict__ sB,
                                         int rowbase, int B, int lane)
{
    const float* xg = x + (size_t)rowbase * FDIM;
    float2 rv[10];
    u64 tails[NTILES];

    // per-lane staging map: item i -> packed goff|soff
    int emap[10];
    #pragma unroll
    for (int i = 0; i < 10; ++i) {
        int id = 32*i + lane;
        int p  = id / 10;
        int rem = id - 10*p;
        int h  = rem / 5;
        int k  = rem - 5*h;
        int goff = (p + h*256) * FDIM + 2*k;
        int soff = p*PSF + h*12 + 2*k;
        emap[i] = goff | (soff << 17);
    }

    auto load_t = [&](int t) {
        const int tb = cF.tbase[t];
        if (tb >= 0) {
            #pragma unroll
            for (int i = 0; i < 10; ++i) {
                int goff = emap[i] & 0x1FFFF;
                if (FULL) {
                    rv[i] = *(const float2*)(xg + goff + tb);
                } else {
                    int row_off = goff / FDIM;
                    float2 v = make_float2(0.0f, 0.0f);
                    if (rowbase + row_off < B) v = *(const float2*)(xg + goff + tb);
                    rv[i] = v;
                }
            }
        } else {
            const int* pp = cF.perm + t * 10;
            #pragma unroll
            for (int i = 0; i < 10; ++i) {
                int id = 32*i + lane;
                int p  = id / 10;
                int rem = id - 10*p;
                int h  = rem / 5;
                int k  = rem - 5*h;
                int row_off = p + h*256;
                float v0 = 0.0f, v1 = 0.0f;
                if (FULL || rowbase + row_off < B) {
                    const float* rp = xg + row_off * FDIM;
                    v0 = rp[pp[2*k]];
                    v1 = rp[pp[2*k+1]];
                }
                rv[i] = make_float2(v0, v1);
            }
        }
    };
    auto store_t = [&](float* dst) {
        #pragma unroll
        for (int i = 0; i < 10; ++i) {
            int soff = emap[i] >> 17;
            *(float2*)(dst + soff) = rv[i];
        }
    };

    // stage tile 0 into A
    load_t(0);
    store_t(sA);
    __syncwarp();

    const float* pA = sA + lane * PSF;
    const float* pB = sB + lane * PSF;

    #pragma unroll
    for (int t = 0; t < NTILES; ++t) {
        if (t < NTILES - 1)
            load_t(t + 1);                      // LDGs in flight over compute

        u64 err = compute_tile_q((t & 1) ? pB : pA, t);
        float e0, e1;
        unpack2(err, e0, e1);
        // 0.5*ln(err*0.1) = (ln2/2)*lg2(err) - 0.5*ln(10)
        tails[t] = pack2(__fmaf_rn(0.34657359f, lg2f(e0), -1.15129255f),
                         __fmaf_rn(0.34657359f, lg2f(e1), -1.15129255f));

        if (t < NTILES - 1)
            store_t((t & 1) ? sA : sB);         // other buffer: no WAR hazard
        __syncwarp();                           // publish for next iteration
    }

    // ---- head: head_out = tails @ MH^T + b_h ----
    u64 ho[NTILES];
    #pragma unroll
    for (int jp = 0; jp < 5; ++jp) {
        ulonglong2 bb = cF.BH[jp];
        u64 a0 = bb.x, a1 = bb.y;
        #pragma unroll
        for (int tt = 0; tt < 5; ++tt) {
            ulonglong2 w0 = cF.MH[(2*jp)   * 5 + tt];
            ulonglong2 w1 = cF.MH[(2*jp+1) * 5 + tt];
            a0 = fma2(tails[2*tt],   w0.x, a0);
            a0 = fma2(tails[2*tt+1], w0.y, a0);
            a1 = fma2(tails[2*tt],   w1.x, a1);
            a1 = fma2(tails[2*tt+1], w1.y, a1);
        }
        ho[2*jp]   = a0;
        ho[2*jp+1] = a1;
    }

    // ---- warp-local output restage (uses buffer A): head then tails ----
    float* slf = sA;
    const long long B10 = (long long)B * NTILES;
    #pragma unroll 1
    for (int r = 0; r < 2; ++r) {
        const u64* src = r ? tails : ho;
        #pragma unroll
        for (int n = 0; n < NTILES; ++n) {
            float a, b;
            unpack2(src[n], a, b);
            slf[lane * 10 + n]       = a;      // rows rowbase..+32
            slf[320 + lane * 10 + n] = b;      // rows rowbase+256..+32
        }
        __syncwarp();
        const long long bound = (long long)(r + 1) * B10;
        #pragma unroll
        for (int i = 0; i < 5; ++i) {
            int q  = lane + 32 * i;            // 0..159 float4 index
            int h  = (q >= 80) ? 1 : 0;
            int qq = q - 80 * h;
            long long off = (long long)r * B10
                          + (long long)(rowbase + h * 256) * 10 + 4 * qq;
            float4 v = *(const float4*)(slf + h * 320 + 4 * qq);
            if (FULL || off + 4 <= bound) {
                *(float4*)(out + off) = v;
            } else {
                const float* vf = (const float*)&v;
                #pragma unroll
                for (int kk = 0; kk < 4; ++kk)
                    if (off + kk < bound) out[off + kk] = vf[kk];
            }
        }
        __syncwarp();
    }
}

__global__ void __launch_bounds__(TPB, 3) kitnet_main(
    const float* __restrict__ x,
    float* __restrict__ out,
    int B)
{
    __shared__ float xs[2][8 * SLICE_F];       // 2 x 28672 B (ping-pong)

    const int tid  = threadIdx.x;
    const int lane = tid & 31;
    const int wid  = tid >> 5;
    const int base = blockIdx.x * RPB;
    const int rowbase = base + wid * 32;
    float* sA = xs[0] + wid * SLICE_F;
    float* sB = xs[1] + wid * SLICE_F;

    if (base + RPB <= B)
        run_rows<true>(x, out, sA, sB, rowbase, B, lane);
    else
        run_rows<false>(x, out, sA, sB, rowbase, B, lane);
}

extern "C" void kernel_launch(void* const* d_in, const int* in_sizes, int n_in,
                              void* d_out, int out_size)
{
    const float* x   = (const float*)d_in[0];
    const float* Wt  = (const float*)d_in[1];
    const float* hbt = (const float*)d_in[2];
    const float* vbt = (const float*)d_in[3];
    const float* Wh  = (const float*)d_in[4];
    const float* hbh = (const float*)d_in[5];
    const float* vbh = (const float*)d_in[6];
    const int*   cls = (const int*)d_in[7];

    const int B = in_sizes[0] / FDIM;
    const int grid = (B + RPB - 1) / RPB;

    kitnet_setup<<<1, TPB>>>(Wt, hbt, vbt, Wh, hbh, vbh, cls);

    void* gfp = nullptr;
    cudaGetSymbolAddress(&gfp, gF);
    cudaMemcpyToSymbolAsync(cF, gfp, sizeof(FoldData), 0,
                            cudaMemcpyDeviceToDevice, 0);

    kitnet_main<<<grid, TPB>>>(x, (float*)d_out, B);
}

// round 11
// speedup vs baseline: 1.1267x; 1.1267x over previous
#include <cuda_runtime.h>
#include <cstddef>

// KitNET_5257039970983 — R10: R7 skeleton exactly (constant-bank weights,
// warp-local staging, no block barriers, unroll-1 tile loop) with the tile
// compute replaced by the triangular quadratic fold err = x'Sx + c'x + k
// (S = M^2, c = 2Mb, k = b'b), two err accumulators for ILP.
// Output: head_out(B,10) then tails(B,10), fp32.

#define NTILES 10
#define CDIM   10
#define HDIM   7
#define FDIM   100
#define TPB    256
#define RPB    512
#define PSTR   11                 // u64 per pair-row (88B, conflict-free LDS/STS)
#define SLICE_U64 (32*PSTR)       // 352 u64 = 2816 B per warp

typedef unsigned long long u64;

// triangular row offsets (ulonglong2 units) within a tile's 35-entry UT block,
// and pair counts per row. Row i = [c_i, U_ii, U_i(i+1), ..., U_i9, pad]
__device__ constexpr int ROFF[10] = {0, 6, 11, 16, 20, 24, 27, 30, 32, 34};
__device__ constexpr int QI[10]   = {6, 5, 5, 4, 4, 3, 3, 2, 2, 1};

struct FoldData {
    ulonglong2 UT[350];   // [t][35] triangular rows, (v,v)-packed
    u64        KT[10];    // (k,k)
    ulonglong2 MH[50];    // head fold [j][i pair]
    ulonglong2 BH[5];
    int perm[100];
    int tbase[10];
    int pad[2];
};

__device__   FoldData gF;
__constant__ FoldData cF;

__device__ __forceinline__ u64 fma2(u64 a, u64 b, u64 c) {
    u64 d;
    asm("fma.rn.f32x2 %0, %1, %2, %3;" : "=l"(d) : "l"(a), "l"(b), "l"(c));
    return d;
}
__device__ __forceinline__ u64 add2(u64 a, u64 b) {
    u64 d;
    asm("add.rn.f32x2 %0, %1, %2;" : "=l"(d) : "l"(a), "l"(b));
    return d;
}
__device__ __forceinline__ u64 pack2(float x, float y) {
    u64 d;
    asm("mov.b64 %0, {%1, %2};" : "=l"(d) : "f"(x), "f"(y));
    return d;
}
__device__ __forceinline__ void unpack2(u64 a, float& x, float& y) {
    asm("mov.b64 {%0, %1}, %2;" : "=f"(x), "=f"(y) : "l"(a));
}

// ================= setup kernel: fold weights into gF (1 block) =================
__global__ void kitnet_setup(const float* __restrict__ Wt,
                             const float* __restrict__ hbt,
                             const float* __restrict__ vbt,
                             const float* __restrict__ Wh,
                             const float* __restrict__ hbh,
                             const float* __restrict__ vbh,
                             const int*   __restrict__ clusters)
{
    __shared__ float sW[700], sHB[70], sVB[100], sWH[70], sHBH[7], sVBH[10];
    __shared__ float sM[1000], sB[100];
    const int tid = threadIdx.x;
    for (int i = tid; i < 700; i += TPB) sW[i]  = Wt[i];
    for (int i = tid; i < 70;  i += TPB) sHB[i] = hbt[i];
    for (int i = tid; i < 100; i += TPB) sVB[i] = vbt[i];
    for (int i = tid; i < 70;  i += TPB) sWH[i] = Wh[i];
    if (tid < HDIM)   sHBH[tid] = hbh[tid];
    if (tid < NTILES) sVBH[tid] = vbh[tid];
    __syncthreads();

    // M = W^T W - I per tile ; b = W^T hb + vb
    for (int i = tid; i < 1000; i += TPB) {
        int t  = i / 100;
        int r  = i - t * 100;
        int co = r / 10;
        int ci = r - co * 10;
        float m = (ci == co) ? -1.0f : 0.0f;
        #pragma unroll
        for (int h = 0; h < HDIM; ++h)
            m += sW[t * 70 + h * 10 + ci] * sW[t * 70 + h * 10 + co];
        sM[i] = m;
    }
    for (int i = tid; i < 100; i += TPB) {
        int t = i / 10, c = i - t * 10;
        float b = sVB[i];
        #pragma unroll
        for (int h = 0; h < HDIM; ++h)
            b += sHB[t * HDIM + h] * sW[t * 70 + h * 10 + c];
        sB[i] = b;
    }
    __syncthreads();

    // quadratic fold: S = M^2 (sym), c = 2Mb, k = b.b ; triangular packing
    if (tid < 100) {
        int t = tid / 10, i = tid - (tid / 10) * 10;
        const float* Mt = sM + t * 100;
        const float* bt = sB + t * 10;
        float c = 0.0f;
        #pragma unroll
        for (int m = 0; m < 10; ++m) c += Mt[i * 10 + m] * bt[m];
        c *= 2.0f;
        float e[12];
        #pragma unroll
        for (int z = 0; z < 12; ++z) e[z] = 0.0f;
        e[0] = c;
        for (int j = i; j < 10; ++j) {
            float s = 0.0f;
            #pragma unroll
            for (int m = 0; m < 10; ++m) s += Mt[i * 10 + m] * Mt[m * 10 + j];
            e[1 + (j - i)] = (j == i) ? s : 2.0f * s;
        }
        int off = t * 35 + ROFF[i];
        int q   = QI[i];
        for (int p = 0; p < q; ++p) {
            ulonglong2 w;
            w.x = pack2(e[2 * p],     e[2 * p]);
            w.y = pack2(e[2 * p + 1], e[2 * p + 1]);
            gF.UT[off + p] = w;
        }
    }
    if (tid < NTILES) {
        const float* bt = sB + tid * 10;
        float k = 0.0f;
        #pragma unroll
        for (int m = 0; m < 10; ++m) k += bt[m] * bt[m];
        gF.KT[tid] = pack2(k, k);
    }

    // head fold
    float2* MH2 = (float2*)gF.MH;
    float2* BH2 = (float2*)gF.BH;
    for (int i = tid; i < CDIM * CDIM; i += TPB) {
        int j = i / 10, ii = i - j * 10;
        float m = 0.0f;
        #pragma unroll
        for (int h = 0; h < HDIM; ++h)
            m += sWH[h * 10 + ii] * sWH[h * 10 + j];
        MH2[i] = make_float2(m, m);
    }
    if (tid < NTILES) {
        float b = sVBH[tid];
        #pragma unroll
        for (int h = 0; h < HDIM; ++h)
            b += sHBH[h] * sWH[h * 10 + tid];
        BH2[tid] = make_float2(b, b);
    }
    for (int i = tid; i < FDIM; i += TPB) gF.perm[i] = clusters[i];
    if (tid < NTILES) {
        const int* pp = clusters + tid * 10;
        int b0 = pp[0];
        bool ok = ((b0 & 1) == 0);
        #pragma unroll
        for (int j = 1; j < 10; ++j) ok = ok && (pp[j] == b0 + j);
        gF.tbase[tid] = ok ? b0 : -1;
    }
}

// ================= main kernel (R7 skeleton) =================

// warp-local staging: one tile's 10 cols for this warp's 32 pairs -> regs
__device__ __forceinline__ void stage_load(const float* __restrict__ x, float rv[20],
                                           int t, int rowbase, int B, int lane)
{
    const int tb = cF.tbase[t];
    if (tb >= 0) {
        #pragma unroll
        for (int i = 0; i < 10; ++i) {
            int id = 32*i + lane;                  // 0..319
            int p  = id / 10;
            int rem = id - 10*p;
            int h  = rem / 5;
            int k  = rem - 5*h;
            int row = rowbase + p + h*256;
            float2 v = make_float2(0.0f, 0.0f);
            if (row < B) v = *(const float2*)(x + (size_t)row*FDIM + tb + 2*k);
            rv[2*i]   = v.x;
            rv[2*i+1] = v.y;
        }
    } else {
        const int* pp = cF.perm + t * 10;
        #pragma unroll
        for (int i = 0; i < 20; ++i) {
            int id = 32*i + lane;                  // 0..639
            int p  = id / 20;
            int rem = id - 20*p;
            int h  = rem / 10;
            int j  = rem - 10*h;
            int row = rowbase + p + h*256;
            float v = 0.0f;
            if (row < B) v = x[(size_t)row*FDIM + pp[j]];
            rv[i] = v;
        }
    }
}

__device__ __forceinline__ void stage_store(float* __restrict__ slf, const float rv[20],
                                            int t, int lane)
{
    const int tb = cF.tbase[t];
    if (tb >= 0) {
        #pragma unroll
        for (int i = 0; i < 10; ++i) {
            int id = 32*i + lane;
            int p  = id / 10;
            int rem = id - 10*p;
            int h  = rem / 5;
            int k  = rem - 5*h;
            slf[p*22 + 4*k + h]     = rv[2*i];
            slf[p*22 + 4*k + 2 + h] = rv[2*i+1];
        }
    } else {
        #pragma unroll
        for (int i = 0; i < 20; ++i) {
            int id = 32*i + lane;
            int p  = id / 20;
            int rem = id - 20*p;
            int h  = rem / 10;
            int j  = rem - 10*h;
            slf[p*22 + 2*j + h] = rv[i];
        }
    }
}

// err = x'Sx + c'x + k from triangular constant block; two err accumulators,
// rows independent (high ILP); t stays a loop variable (unroll-1 outside).
__device__ __forceinline__ u64 compute_tile_q(const u64 xc[CDIM], int t)
{
    const ulonglong2* R = cF.UT + t * 35;
    u64 err0 = cF.KT[t];
    u64 err1 = 0ull;
    #pragma unroll
    for (int i = 0; i < 10; ++i) {
        const ulonglong2* Ri = R + ROFF[i];
        ulonglong2 w = Ri[0];
        u64 acc = w.x;                       // c_i
        acc = fma2(xc[i], w.y, acc);         // + U_ii * x_i
        #pragma unroll
        for (int p = 1; p < QI[i]; ++p) {
            w = Ri[p];
            acc = fma2(xc[i + 2*p - 1], w.x, acc);
            if (i + 2*p <= 9)
                acc = fma2(xc[i + 2*p], w.y, acc);
        }
        if (i & 1) err1 = fma2(xc[i], acc, err1);
        else       err0 = fma2(xc[i], acc, err0);
    }
    return add2(err0, err1);
}

__global__ void __launch_bounds__(TPB, 3) kitnet_main(
    const float* __restrict__ x,
    float* __restrict__ out,
    int B)
{
    __shared__ u64 xs[8 * SLICE_U64];          // 22528 B

    const int tid  = threadIdx.x;
    const int lane = tid & 31;
    const int wid  = tid >> 5;
    const int base = blockIdx.x * RPB;

    const int rowbase = base + wid * 32;
    u64*   xsw = xs + wid * SLICE_U64;
    float* slf = (float*)xsw;

    float rv[20];
    u64 tails[NTILES];

    // stage tile 0
    stage_load(x, rv, 0, rowbase, B, lane);
    stage_store(slf, rv, 0, lane);
    __syncwarp();

    #pragma unroll 1
    for (int t = 0; t < NTILES; ++t) {
        if (t < NTILES - 1)
            stage_load(x, rv, t + 1, rowbase, B, lane);

        u64 xc[CDIM];
        #pragma unroll
        for (int j = 0; j < CDIM; ++j) xc[j] = xsw[lane * PSTR + j];

        u64 err = compute_tile_q(xc, t);
        float e0, e1;
        unpack2(err, e0, e1);
        // 0.5*log(0.1*e) = 0.5*log(e) - 0.5*log(10)
        tails[t] = pack2(__fmaf_rn(0.5f, __logf(e0), -1.15129255f),
                         __fmaf_rn(0.5f, __logf(e1), -1.15129255f));

        __syncwarp();                          // all lanes done reading slice
        if (t < NTILES - 1)
            stage_store(slf, rv, t + 1, lane);
        __syncwarp();                          // writes visible for next xc load
    }

    // ---- head: head_out = tails @ MH^T + b_h (constant-bank weights) ----
    u64 ho[NTILES];
    #pragma unroll
    for (int jp = 0; jp < 5; ++jp) {
        ulonglong2 bb = cF.BH[jp];
        u64 a0 = bb.x, a1 = bb.y;
        #pragma unroll
        for (int tt = 0; tt < 5; ++tt) {
            ulonglong2 w0 = cF.MH[(2*jp)   * 5 + tt];
            ulonglong2 w1 = cF.MH[(2*jp+1) * 5 + tt];
            a0 = fma2(tails[2*tt],   w0.x, a0);
            a0 = fma2(tails[2*tt+1], w0.y, a0);
            a1 = fma2(tails[2*tt],   w1.x, a1);
            a1 = fma2(tails[2*tt+1], w1.y, a1);
        }
        ho[2*jp]   = a0;
        ho[2*jp+1] = a1;
    }

    // ---- warp-local output restage: round 0 = head, round 1 = tails ----
    const long long B10 = (long long)B * NTILES;
    #pragma unroll 1
    for (int r = 0; r < 2; ++r) {
        const u64* src = r ? tails : ho;
        #pragma unroll
        for (int n = 0; n < NTILES; ++n) {
            float a, b;
            unpack2(src[n], a, b);
            slf[lane * 10 + n]       = a;      // rows rowbase..+32
            slf[320 + lane * 10 + n] = b;      // rows rowbase+256..+32
        }
        __syncwarp();
        const long long bound = (long long)(r + 1) * B10;
        #pragma unroll
        for (int i = 0; i < 5; ++i) {
            int q  = lane + 32 * i;            // 0..159 float4 index
            int h  = (q >= 80) ? 1 : 0;
            int qq = q - 80 * h;
            long long off = (long long)r * B10
                          + (long long)(rowbase + h * 256) * 10 + 4 * qq;
            float4 v = *(const float4*)(slf + h * 320 + 4 * qq);
            if (off + 4 <= bound) {
                *(float4*)(out + off) = v;
            } else {
                const float* vf = (const float*)&v;
                #pragma unroll
                for (int kk = 0; kk < 4; ++kk)
                    if (off + kk < bound) out[off + kk] = vf[kk];
            }
        }
        __syncwarp();
    }
}

extern "C" void kernel_launch(void* const* d_in, const int* in_sizes, int n_in,
                              void* d_out, int out_size)
{
    const float* x   = (const float*)d_in[0];
    const float* Wt  = (const float*)d_in[1];
    const float* hbt = (const float*)d_in[2];
    const float* vbt = (const float*)d_in[3];
    const float* Wh  = (const float*)d_in[4];
    const float* hbh = (const float*)d_in[5];
    const float* vbh = (const float*)d_in[6];
    const int*   cls = (const int*)d_in[7];

    const int B = in_sizes[0] / FDIM;
    const int grid = (B + RPB - 1) / RPB;

    kitnet_setup<<<1, TPB>>>(Wt, hbt, vbt, Wh, hbh, vbh, cls);

    void* gfp = nullptr;
    cudaGetSymbolAddress(&gfp, gF);
    cudaMemcpyToSymbolAsync(cF, gfp, sizeof(FoldData), 0,
                            cudaMemcpyDeviceToDevice, 0);

    kitnet_main<<<grid, TPB>>>(x, (float*)d_out, B);
}